// round 13
// baseline (speedup 1.0000x reference)
#include <cuda_runtime.h>
#include <cstdint>

#define NPTS 12288
#define DW   384           // 32-bit words per adjacency row (12288/32)
#define EPS2 0.25f
#define MIN_SAMPLES 5
#define JT   256           // square tile side in k_adj
#define NTILE 48           // NPTS / JT
#define NTRI  (NTILE * (NTILE + 1) / 2)   // 1176 upper-tri tiles

typedef unsigned long long ull;

// ---------------- device scratch (no dynamic allocation allowed) -------------
__device__ unsigned g_adj[NPTS * DW];   // 18.9 MB adjacency bitmap
__device__ int      g_parent[NPTS];     // union-find parents
__device__ int      g_core[NPTS];       // core mask
__device__ unsigned g_corebits[DW];     // core mask, bit-packed
__device__ int      g_lbl[NPTS];        // final root per core (NPTS else)
__device__ int      g_root[NPTS];       // border root (non-core rows)
__device__ int      g_rank[NPTS];       // cumsum(is_root)-1

// ---------------- f32x2 packed-math helpers (sm_100+) ------------------------
__device__ __forceinline__ ull pack2(float lo, float hi) {
    ull r;
    asm("mov.b64 %0, {%1, %2};" : "=l"(r) : "f"(lo), "f"(hi));
    return r;
}
__device__ __forceinline__ ull mul2(ull a, ull b) {
    ull d;
    asm("mul.rn.f32x2 %0, %1, %2;" : "=l"(d) : "l"(a), "l"(b));
    return d;
}
__device__ __forceinline__ ull fma2(ull a, ull b, ull c) {
    ull d;
    asm("fma.rn.f32x2 %0, %1, %2, %3;" : "=l"(d) : "l"(a), "l"(b), "l"(c));
    return d;
}
__device__ __forceinline__ ull add2(ull a, ull b) {
    ull d;
    asm("add.rn.f32x2 %0, %1, %2;" : "=l"(d) : "l"(a), "l"(b));
    return d;
}
__device__ __forceinline__ void unpack2(ull v, float& lo, float& hi) {
    asm("mov.b64 {%0, %1}, %2;" : "=f"(lo), "=f"(hi) : "l"(v));
}

// squared norm with the same sequential FMA chain as the distance dot products
__device__ __forceinline__ float norm8(float4 a, float4 b) {
    float s = a.x * a.x;
    s = fmaf(a.y, a.y, s);
    s = fmaf(a.z, a.z, s);
    s = fmaf(a.w, a.w, s);
    s = fmaf(b.x, b.x, s);
    s = fmaf(b.y, b.y, s);
    s = fmaf(b.z, b.z, s);
    s = fmaf(b.w, b.w, s);
    return s;
}

// 32x32 bit-matrix transpose within a warp (5 block-swap stages).
__device__ __forceinline__ unsigned bit_transpose32(unsigned x, int lane) {
    const unsigned masks[5] = {0xAAAAAAAAu, 0xCCCCCCCCu, 0xF0F0F0F0u,
                               0xFF00FF00u, 0xFFFF0000u};
#pragma unroll
    for (int si = 0; si < 5; si++) {
        int s = 1 << si;
        unsigned m = masks[si];
        unsigned y = __shfl_xor_sync(0xffffffffu, x, s);
        if (lane & s)
            x = (x & m) | ((y & m) >> s);
        else
            x = (x & ~m) | ((y & ~m) << s);
    }
    return x;
}

// ---------------- K1: adjacency bitmap (triangular + pre-dup smem) -----------
// Triangular 1D grid over 256x256 tiles (bx >= by). 8 warps; warp w owns
// j-chunk [jbase+32w, +32); lane l owns rows i0+l+32r, r=0..7, as 4 f32x2
// row-pairs. j-points staged in smem PRE-DUPLICATED ((j.d, j.d) per dim), so
// the inner loop is 5 broadcast LDS + pure packed FMAs (no per-iter MOVs) —
// the R4 inner loop, which beats the 3-LDS+17-MOV variant on issue slots.
// Off-diagonal tiles also write the mirrored tile via warp bit-transpose.
__global__ void __launch_bounds__(256) k_adj(const float* __restrict__ X) {
    // decode linear tile id -> (by, bx) with bx >= by (row-major upper tri)
    int tid_lin = blockIdx.x;
    float ff = __int2float_rn(tid_lin);
    int by = __float2int_rd((2.0f * NTILE + 1.0f -
                             sqrtf((2.0f * NTILE + 1.0f) * (2.0f * NTILE + 1.0f)
                                   - 8.0f * ff)) * 0.5f);
    while ((by + 1) * (2 * NTILE - by) / 2 <= tid_lin) by++;
    while (by * (2 * NTILE - by + 1) / 2 > tid_lin) by--;
    int bx = by + (tid_lin - by * (2 * NTILE - by + 1) / 2);

    __shared__ __align__(16) ull sj[JT][8];   // 16 KB: (j.d, j.d) per dim
    __shared__ ull sjq[JT];                   //  2 KB: (sq_j, sq_j)

    int t = threadIdx.x;
    int jbase = bx * JT;
    int ibase = by * JT;
    const float4* xv = (const float4*)X;

    {
        float4 a = xv[(jbase + t) * 2 + 0];
        float4 b = xv[(jbase + t) * 2 + 1];
        sj[t][0] = pack2(a.x, a.x); sj[t][1] = pack2(a.y, a.y);
        sj[t][2] = pack2(a.z, a.z); sj[t][3] = pack2(a.w, a.w);
        sj[t][4] = pack2(b.x, b.x); sj[t][5] = pack2(b.y, b.y);
        sj[t][6] = pack2(b.z, b.z); sj[t][7] = pack2(b.w, b.w);
        float n = norm8(a, b);
        sjq[t] = pack2(n, n);
    }
    __syncthreads();

    int wid = t >> 5, lane = t & 31;
    int i0 = ibase + lane;                    // rows i0 + 32r, r = 0..7

    ull rp[4][8], sid[4];
#pragma unroll
    for (int p = 0; p < 4; p++) {
        int ra = i0 + 32 * (2 * p), rb = i0 + 32 * (2 * p + 1);
        float4 a0 = xv[ra * 2 + 0], b0 = xv[ra * 2 + 1];
        float4 a1 = xv[rb * 2 + 0], b1 = xv[rb * 2 + 1];
        sid[p] = pack2(norm8(a0, b0), norm8(a1, b1));
        rp[p][0] = pack2(a0.x, a1.x); rp[p][1] = pack2(a0.y, a1.y);
        rp[p][2] = pack2(a0.z, a1.z); rp[p][3] = pack2(a0.w, a1.w);
        rp[p][4] = pack2(b0.x, b1.x); rp[p][5] = pack2(b0.y, b1.y);
        rp[p][6] = pack2(b0.z, b1.z); rp[p][7] = pack2(b0.w, b1.w);
    }
    ull neg2 = pack2(-2.0f, -2.0f);

    int kb = wid * 32;
    unsigned bits[8] = {0, 0, 0, 0, 0, 0, 0, 0};
#pragma unroll 2
    for (int k = 0; k < 32; k++) {
        const ulonglong2* jp = (const ulonglong2*)sj[kb + k];
        ulonglong2 q01 = jp[0];   // broadcast LDS.128 (all lanes same addr)
        ulonglong2 q23 = jp[1];
        ulonglong2 q45 = jp[2];
        ulonglong2 q67 = jp[3];
        ull sq = sjq[kb + k];
        unsigned kbit = 1u << k;
#pragma unroll
        for (int p = 0; p < 4; p++) {
            // per row lane: mul dim0 then fma dims 1..7 (exact ref rounding)
            ull acc = mul2(rp[p][0], q01.x);
            acc = fma2(rp[p][1], q01.y, acc);
            acc = fma2(rp[p][2], q23.x, acc);
            acc = fma2(rp[p][3], q23.y, acc);
            acc = fma2(rp[p][4], q45.x, acc);
            acc = fma2(rp[p][5], q45.y, acc);
            acc = fma2(rp[p][6], q67.x, acc);
            acc = fma2(rp[p][7], q67.y, acc);
            ull t2 = fma2(acc, neg2, add2(sq, sid[p]));   // (si+sj) - 2*dot
            float lo, hi;
            unpack2(t2, lo, hi);
            if (lo <= EPS2) bits[2 * p]     |= kbit;
            if (hi <= EPS2) bits[2 * p + 1] |= kbit;
        }
    }

    int col = bx * 8 + wid;
#pragma unroll
    for (int r = 0; r < 8; r++)
        g_adj[(i0 + 32 * r) * DW + col] = bits[r];

    if (bx != by) {
        int jrow = jbase + kb + lane;
#pragma unroll
        for (int r = 0; r < 8; r++) {
            unsigned tw = bit_transpose32(bits[r], lane);
            g_adj[jrow * DW + (by * 8 + r)] = tw;
        }
    }
}

// ---------------- K2: density -> core mask + bit-pack + parent init ----------
__global__ void __launch_bounds__(1024) k_core(void) {
    __shared__ int sc[32];
    int wid = threadIdx.x >> 5, lane = threadIdx.x & 31;
    int i = blockIdx.x * 32 + wid;
    const uint4* row = (const uint4*)&g_adj[i * DW];
    int s = 0;
#pragma unroll
    for (int w = lane; w < DW / 4; w += 32) {
        uint4 v = row[w];
        s += __popc(v.x) + __popc(v.y) + __popc(v.z) + __popc(v.w);
    }
#pragma unroll
    for (int o = 16; o; o >>= 1) s += __shfl_down_sync(0xffffffffu, s, o);
    if (lane == 0) {
        int c = (s >= MIN_SAMPLES) ? 1 : 0;
        sc[wid] = c;
        g_core[i] = c;
        g_parent[i] = i;
    }
    __syncthreads();
    if (wid == 0) {
        unsigned b = __ballot_sync(0xffffffffu, sc[lane] != 0);
        if (lane == 0) g_corebits[blockIdx.x] = b;
    }
}

// ---------------- union-find -------------------------------------------------
__device__ __forceinline__ int uf_find(volatile int* p, int x) {
    int px = p[x];
    while (px != x) {
        int g = p[px];
        if (g != px) p[x] = g;   // path halving; benign race
        x = g;
        px = p[x];
    }
    return x;
}

__device__ __forceinline__ void uf_union(int* p, int a, int b) {
    volatile int* vp = p;
    while (true) {
        a = uf_find(vp, a);
        b = uf_find(vp, b);
        if (a == b) return;
        int hi = a > b ? a : b;
        int lo = a > b ? b : a;
        int old = atomicCAS(&p[hi], hi, lo);
        if (old == hi) return;   // hooked larger root under smaller -> root = min idx
        a = lo; b = old;
    }
}

__device__ __forceinline__ int uf_find_ro(const volatile int* p, int x) {
    int px;
    while ((px = p[x]) != x) x = px;
    return x;
}

// ---------------- K3: atomic-free forest init (FULL-row first smaller nbr) ---
__global__ void __launch_bounds__(256) k_init(void) {
    int wid = threadIdx.x >> 5, lane = threadIdx.x & 31;
    int i = blockIdx.x * 8 + wid;
    if (!g_core[i]) return;
    int iw = i >> 5;
    for (int base = 0; base <= iw; base += 32) {
        int w = base + lane;
        unsigned word = 0;
        if (w <= iw) {
            word = g_adj[i * DW + w] & g_corebits[w];
            if (w == iw) {
                int r = i & 31;
                word &= r ? ((1u << r) - 1u) : 0u;   // only j < i
            }
        }
        unsigned nz = __ballot_sync(0xffffffffu, word != 0);
        if (nz) {
            int w0 = __ffs(nz) - 1;
            unsigned v0 = __shfl_sync(0xffffffffu, word, w0);
            if (lane == 0) g_parent[i] = (base + w0) * 32 + __ffs(v0) - 1;
            return;
        }
    }
}

// ---------------- K4: flatten (no hooks in flight -> race-free) --------------
__global__ void k_flat(void) {
    int i = blockIdx.x * blockDim.x + threadIdx.x;
    if (i >= NPTS) return;
    if (g_core[i]) g_parent[i] = uf_find_ro(g_parent, i);
}

// ---------------- K5: hook round — min neighbor root via ONE atomicMin -------
__global__ void __launch_bounds__(256) k_hook(void) {
    int wid = threadIdx.x >> 5, lane = threadIdx.x & 31;
    int i = blockIdx.x * 8 + wid;
    if (!g_core[i]) return;
    int ri = g_parent[i];                      // flat root of i
    int m = ri;
#pragma unroll
    for (int w = lane; w < DW; w += 32) {
        unsigned word = __ldg(&g_adj[i * DW + w]) & __ldg(&g_corebits[w]);
        while (word) {
            int bpos = __ffs(word) - 1;
            word &= word - 1;
            m = min(m, g_parent[w * 32 + bpos]);
        }
    }
#pragma unroll
    for (int o = 16; o; o >>= 1) m = min(m, __shfl_down_sync(0xffffffffu, m, o));
    if (lane == 0 && m < ri) atomicMin(&g_parent[ri], m);
}

// ---------------- K6: full edge pass (guaranteed closer; nearly all skip) ----
__global__ void __launch_bounds__(256) k_union2(void) {
    int wid = threadIdx.x >> 5, lane = threadIdx.x & 31;
    int i = blockIdx.x * 8 + wid;
    if (!g_core[i]) return;
    int ri = uf_find(g_parent, i);
    int iw = i >> 5;
    for (int w = iw + lane; w < DW; w += 32) {
        unsigned word = __ldg(&g_adj[i * DW + w]) & __ldg(&g_corebits[w]);
        if (w == iw) {
            int r = i & 31;
            word &= (r == 31) ? 0u : (0xffffffffu << (r + 1));   // keep only j > i
        }
        while (word) {
            int bpos = __ffs(word) - 1;
            word &= word - 1;
            int j = w * 32 + bpos;
            int pj = g_parent[j];
            if (pj != ri && j != ri) uf_union(g_parent, ri, j);
        }
    }
}

// ---------------- K7: resolve — flatten cores + border minima (one pass) -----
__global__ void __launch_bounds__(256) k_resolve(void) {
    int wid = threadIdx.x >> 5, lane = threadIdx.x & 31;
    int i = blockIdx.x * 8 + wid;
    if (g_core[i]) {
        if (lane == 0) g_lbl[i] = uf_find(g_parent, i);
        return;
    }
    const unsigned* row = &g_adj[i * DW];
    int m = NPTS;
#pragma unroll
    for (int w = lane; w < DW; w += 32) {
        unsigned word = row[w] & __ldg(&g_corebits[w]);
        while (word) {
            int bpos = __ffs(word) - 1;
            word &= word - 1;
            m = min(m, uf_find_ro(g_parent, w * 32 + bpos));
        }
    }
#pragma unroll
    for (int o = 16; o; o >>= 1) m = min(m, __shfl_down_sync(0xffffffffu, m, o));
    if (lane == 0) {
        g_root[i] = m;     // NPTS = noise
        g_lbl[i] = NPTS;
    }
}

// ---------------- K8: rank scan + final labels (single block) ----------------
__global__ void __launch_bounds__(1024) k_final(int* __restrict__ labels) {
    __shared__ int wsum[32];
    __shared__ int s_carry;
    int t = threadIdx.x, wid = t >> 5, lane = t & 31;
    if (t == 0) s_carry = 0;
    __syncthreads();

    for (int c = 0; c < 12; c++) {
        int e = c * 1024 + t;
        int r = g_lbl[e];                       // final root (core) or NPTS
        int v = (r == e) ? 1 : 0;               // is_root
        unsigned bal = __ballot_sync(0xffffffffu, v);
        int pre = __popc(bal & (0xffffffffu >> (31 - lane)));
        if (lane == 31) wsum[wid] = pre;
        __syncthreads();
        if (wid == 0) {
            int x = wsum[lane];
#pragma unroll
            for (int o = 1; o < 32; o <<= 1) {
                int y = __shfl_up_sync(0xffffffffu, x, o);
                if (lane >= o) x += y;
            }
            wsum[lane] = x;
        }
        __syncthreads();
        int base = s_carry + ((wid > 0) ? wsum[wid - 1] : 0);
        g_rank[e] = base + pre - 1;
        __syncthreads();
        if (t == 0) s_carry += wsum[31];
        __syncthreads();
    }

    for (int c = 0; c < 12; c++) {
        int e = c * 1024 + t;
        int r = g_lbl[e];
        if (r >= NPTS) r = g_root[e];           // border/noise
        labels[e] = (r < NPTS) ? g_rank[r] : -1;
    }
}

// ---------------- launcher ----------------------------------------------------
extern "C" void kernel_launch(void* const* d_in, const int* in_sizes, int n_in,
                              void* d_out, int out_size) {
    (void)in_sizes; (void)n_in; (void)out_size;
    const float* X = (const float*)d_in[0];
    int* labels = (int*)d_out;

    k_adj<<<NTRI, 256>>>(X);
    k_core<<<384, 1024>>>();
    k_init<<<NPTS / 8, 256>>>();
    k_flat<<<48, 256>>>();
    k_hook<<<NPTS / 8, 256>>>();
    k_flat<<<48, 256>>>();
    k_union2<<<NPTS / 8, 256>>>();
    k_resolve<<<NPTS / 8, 256>>>();
    k_final<<<1, 1024>>>(labels);
}

// round 14
// speedup vs baseline: 1.0032x; 1.0032x over previous
#include <cuda_runtime.h>
#include <cstdint>

#define NPTS 12288
#define DW   384           // 32-bit words per adjacency row (12288/32)
#define EPS2 0.25f
#define MIN_SAMPLES 5
#define JT   256           // square tile side in k_adj
#define NTILE 48           // NPTS / JT
#define NTRI  (NTILE * (NTILE + 1) / 2)   // 1176 upper-tri tiles

#define CC_GRID   148
#define CC_WARPS  (CC_GRID * 32)          // 4736 global warps

typedef unsigned long long ull;

// ---------------- device scratch (no dynamic allocation allowed) -------------
__device__ unsigned g_adj[NPTS * DW];   // 18.9 MB adjacency bitmap
__device__ int      g_parent[NPTS];     // union-find parents
__device__ int      g_core[NPTS];       // core mask
__device__ unsigned g_corebits[DW];     // core mask, bit-packed
__device__ int      g_lbl[NPTS];        // final root per core (NPTS else)
__device__ int      g_root[NPTS];       // border root (non-core rows)
__device__ int      g_rank[NPTS];       // cumsum(is_root)-1

// software grid barrier state (generation-based; survives graph replays:
// count returns to 0 after every barrier, gen only grows)
__device__ volatile int g_bar_gen;
__device__ int          g_bar_count;

// ---------------- f32x2 packed-math helpers (sm_100+) ------------------------
__device__ __forceinline__ ull pack2(float lo, float hi) {
    ull r;
    asm("mov.b64 %0, {%1, %2};" : "=l"(r) : "f"(lo), "f"(hi));
    return r;
}
__device__ __forceinline__ ull mul2(ull a, ull b) {
    ull d;
    asm("mul.rn.f32x2 %0, %1, %2;" : "=l"(d) : "l"(a), "l"(b));
    return d;
}
__device__ __forceinline__ ull fma2(ull a, ull b, ull c) {
    ull d;
    asm("fma.rn.f32x2 %0, %1, %2, %3;" : "=l"(d) : "l"(a), "l"(b), "l"(c));
    return d;
}
__device__ __forceinline__ ull add2(ull a, ull b) {
    ull d;
    asm("add.rn.f32x2 %0, %1, %2;" : "=l"(d) : "l"(a), "l"(b));
    return d;
}
__device__ __forceinline__ void unpack2(ull v, float& lo, float& hi) {
    asm("mov.b64 {%0, %1}, %2;" : "=f"(lo), "=f"(hi) : "l"(v));
}

__device__ __forceinline__ float norm8(float4 a, float4 b) {
    float s = a.x * a.x;
    s = fmaf(a.y, a.y, s);
    s = fmaf(a.z, a.z, s);
    s = fmaf(a.w, a.w, s);
    s = fmaf(b.x, b.x, s);
    s = fmaf(b.y, b.y, s);
    s = fmaf(b.z, b.z, s);
    s = fmaf(b.w, b.w, s);
    return s;
}

// 32x32 bit-matrix transpose within a warp (5 block-swap stages).
__device__ __forceinline__ unsigned bit_transpose32(unsigned x, int lane) {
    const unsigned masks[5] = {0xAAAAAAAAu, 0xCCCCCCCCu, 0xF0F0F0F0u,
                               0xFF00FF00u, 0xFFFF0000u};
#pragma unroll
    for (int si = 0; si < 5; si++) {
        int s = 1 << si;
        unsigned m = masks[si];
        unsigned y = __shfl_xor_sync(0xffffffffu, x, s);
        if (lane & s)
            x = (x & m) | ((y & m) >> s);
        else
            x = (x & ~m) | ((y & ~m) << s);
    }
    return x;
}

// ---------------- K1: adjacency bitmap (triangular, R12-proven inner loop) ---
__global__ void __launch_bounds__(256) k_adj(const float* __restrict__ X) {
    // decode linear tile id -> (by, bx) with bx >= by (row-major upper tri)
    int tid_lin = blockIdx.x;
    float ff = __int2float_rn(tid_lin);
    int by = __float2int_rd((2.0f * NTILE + 1.0f -
                             sqrtf((2.0f * NTILE + 1.0f) * (2.0f * NTILE + 1.0f)
                                   - 8.0f * ff)) * 0.5f);
    while ((by + 1) * (2 * NTILE - by) / 2 <= tid_lin) by++;
    while (by * (2 * NTILE - by + 1) / 2 > tid_lin) by--;
    int bx = by + (tid_lin - by * (2 * NTILE - by + 1) / 2);

    __shared__ __align__(16) float4 sjd[JT][3];   // [0]=dims0-3 [1]=dims4-7 [2].x=norm

    int t = threadIdx.x;
    int jbase = bx * JT;
    int ibase = by * JT;
    const float4* xv = (const float4*)X;

    {
        float4 a = xv[(jbase + t) * 2 + 0];
        float4 b = xv[(jbase + t) * 2 + 1];
        sjd[t][0] = a;
        sjd[t][1] = b;
        sjd[t][2] = make_float4(norm8(a, b), 0.f, 0.f, 0.f);
    }
    __syncthreads();

    int wid = t >> 5, lane = t & 31;
    int i0 = ibase + lane;                    // rows i0 + 32r, r = 0..7

    ull rp[4][8], sid[4];
#pragma unroll
    for (int p = 0; p < 4; p++) {
        int ra = i0 + 32 * (2 * p), rb = i0 + 32 * (2 * p + 1);
        float4 a0 = xv[ra * 2 + 0], b0 = xv[ra * 2 + 1];
        float4 a1 = xv[rb * 2 + 0], b1 = xv[rb * 2 + 1];
        sid[p] = pack2(norm8(a0, b0), norm8(a1, b1));
        rp[p][0] = pack2(a0.x, a1.x); rp[p][1] = pack2(a0.y, a1.y);
        rp[p][2] = pack2(a0.z, a1.z); rp[p][3] = pack2(a0.w, a1.w);
        rp[p][4] = pack2(b0.x, b1.x); rp[p][5] = pack2(b0.y, b1.y);
        rp[p][6] = pack2(b0.z, b1.z); rp[p][7] = pack2(b0.w, b1.w);
    }
    ull neg2 = pack2(-2.0f, -2.0f);

    int kb = wid * 32;
    unsigned bits[8] = {0, 0, 0, 0, 0, 0, 0, 0};
#pragma unroll 4
    for (int k = 0; k < 32; k++) {
        float4 c = sjd[kb + k][0];
        float4 d = sjd[kb + k][1];
        float n  = sjd[kb + k][2].x;
        ull q0 = pack2(c.x, c.x), q1 = pack2(c.y, c.y);
        ull q2 = pack2(c.z, c.z), q3 = pack2(c.w, c.w);
        ull q4 = pack2(d.x, d.x), q5 = pack2(d.y, d.y);
        ull q6 = pack2(d.z, d.z), q7 = pack2(d.w, d.w);
        ull sq = pack2(n, n);
        unsigned kbit = 1u << k;
#pragma unroll
        for (int p = 0; p < 4; p++) {
            ull acc = mul2(rp[p][0], q0);
            acc = fma2(rp[p][1], q1, acc);
            acc = fma2(rp[p][2], q2, acc);
            acc = fma2(rp[p][3], q3, acc);
            acc = fma2(rp[p][4], q4, acc);
            acc = fma2(rp[p][5], q5, acc);
            acc = fma2(rp[p][6], q6, acc);
            acc = fma2(rp[p][7], q7, acc);
            ull t2 = fma2(acc, neg2, add2(sq, sid[p]));   // (si+sj) - 2*dot
            float lo, hi;
            unpack2(t2, lo, hi);
            if (lo <= EPS2) bits[2 * p]     |= kbit;
            if (hi <= EPS2) bits[2 * p + 1] |= kbit;
        }
    }

    int col = bx * 8 + wid;
#pragma unroll
    for (int r = 0; r < 8; r++)
        g_adj[(i0 + 32 * r) * DW + col] = bits[r];

    if (bx != by) {
        int jrow = jbase + kb + lane;
#pragma unroll
        for (int r = 0; r < 8; r++) {
            unsigned tw = bit_transpose32(bits[r], lane);
            g_adj[jrow * DW + (by * 8 + r)] = tw;
        }
    }
}

// ---------------- union-find -------------------------------------------------
__device__ __forceinline__ int uf_find(volatile int* p, int x) {
    int px = p[x];
    while (px != x) {
        int g = p[px];
        if (g != px) p[x] = g;   // path halving; benign race
        x = g;
        px = p[x];
    }
    return x;
}

__device__ __forceinline__ void uf_union(int* p, int a, int b) {
    volatile int* vp = p;
    while (true) {
        a = uf_find(vp, a);
        b = uf_find(vp, b);
        if (a == b) return;
        int hi = a > b ? a : b;
        int lo = a > b ? b : a;
        int old = atomicCAS(&p[hi], hi, lo);
        if (old == hi) return;
        a = lo; b = old;
    }
}

__device__ __forceinline__ int uf_find_ro(const volatile int* p, int x) {
    int px;
    while ((px = p[x]) != x) x = px;
    return x;
}

// ---------------- software grid barrier (gen-based) ---------------------------
// __threadfence() is gpu-scope -> CCTL.IVALL: flushes pending writes to L2 and
// invalidates L1D, so plain loads after the barrier see other SMs' writes.
__device__ __forceinline__ void grid_sync() {
    __threadfence();
    __syncthreads();
    if (threadIdx.x == 0) {
        int gen = g_bar_gen;
        if (atomicAdd(&g_bar_count, 1) == (int)gridDim.x - 1) {
            g_bar_count = 0;
            __threadfence();
            g_bar_gen = gen + 1;
        } else {
            while (g_bar_gen == gen) { }
        }
    }
    __syncthreads();
    __threadfence();
}

// ---------------- K2: the whole CC pipeline in ONE persistent kernel ---------
__global__ void __launch_bounds__(1024, 1) k_cc(int* __restrict__ labels) {
    __shared__ int wsum[32];
    __shared__ int s_carry;

    int tid  = threadIdx.x;
    int lane = tid & 31;
    int wid  = tid >> 5;                     // warp in block, 0..31
    int wg   = blockIdx.x * 32 + wid;        // global warp, 0..4735
    int gtid = blockIdx.x * 1024 + tid;      // global thread

    // ---- phase 1: density -> core mask + parent init ------------------------
    for (int i = wg; i < NPTS; i += CC_WARPS) {
        const uint4* row = (const uint4*)&g_adj[i * DW];
        int s = 0;
#pragma unroll
        for (int w = lane; w < DW / 4; w += 32) {
            uint4 v = row[w];
            s += __popc(v.x) + __popc(v.y) + __popc(v.z) + __popc(v.w);
        }
#pragma unroll
        for (int o = 16; o; o >>= 1) s += __shfl_down_sync(0xffffffffu, s, o);
        if (lane == 0) {
            g_core[i] = (s >= MIN_SAMPLES) ? 1 : 0;
            g_parent[i] = i;
        }
    }
    grid_sync();

    // ---- phase 2: pack core bits --------------------------------------------
    if (wg < DW) {
        int c = g_core[wg * 32 + lane];
        unsigned b = __ballot_sync(0xffffffffu, c != 0);
        if (lane == 0) g_corebits[wg] = b;
    }
    grid_sync();

    // ---- phase 3: atomic-free forest init (first smaller core neighbor) -----
    for (int i = wg; i < NPTS; i += CC_WARPS) {
        if (!g_core[i]) continue;
        int iw = i >> 5;
        for (int base = 0; base <= iw; base += 32) {
            int w = base + lane;
            unsigned word = 0;
            if (w <= iw) {
                word = g_adj[i * DW + w] & g_corebits[w];
                if (w == iw) {
                    int r = i & 31;
                    word &= r ? ((1u << r) - 1u) : 0u;   // only j < i
                }
            }
            unsigned nz = __ballot_sync(0xffffffffu, word != 0);
            if (nz) {
                int w0 = __ffs(nz) - 1;
                unsigned v0 = __shfl_sync(0xffffffffu, word, w0);
                if (lane == 0) g_parent[i] = (base + w0) * 32 + __ffs(v0) - 1;
                break;
            }
        }
    }
    grid_sync();

    // ---- phase 4: flatten (race-free: no hooks in flight) --------------------
    if (gtid < NPTS && g_core[gtid]) g_parent[gtid] = uf_find_ro(g_parent, gtid);
    grid_sync();

    // ---- phase 5: hook — min neighbor root via ONE atomicMin -----------------
    for (int i = wg; i < NPTS; i += CC_WARPS) {
        if (!g_core[i]) continue;
        int ri = g_parent[i];
        int m = ri;
#pragma unroll
        for (int w = lane; w < DW; w += 32) {
            unsigned word = g_adj[i * DW + w] & g_corebits[w];
            while (word) {
                int bpos = __ffs(word) - 1;
                word &= word - 1;
                m = min(m, g_parent[w * 32 + bpos]);
            }
        }
#pragma unroll
        for (int o = 16; o; o >>= 1) m = min(m, __shfl_down_sync(0xffffffffu, m, o));
        if (lane == 0 && m < ri) atomicMin(&g_parent[ri], m);
    }
    grid_sync();

    // ---- phase 6: flatten ----------------------------------------------------
    if (gtid < NPTS && g_core[gtid]) g_parent[gtid] = uf_find_ro(g_parent, gtid);
    grid_sync();

    // ---- phase 7: full edge pass (guaranteed closer; nearly all skip) --------
    for (int i = wg; i < NPTS; i += CC_WARPS) {
        if (!g_core[i]) continue;
        int ri = uf_find(g_parent, i);
        int iw = i >> 5;
        for (int w = iw + lane; w < DW; w += 32) {
            unsigned word = g_adj[i * DW + w] & g_corebits[w];
            if (w == iw) {
                int r = i & 31;
                word &= (r == 31) ? 0u : (0xffffffffu << (r + 1));   // only j > i
            }
            while (word) {
                int bpos = __ffs(word) - 1;
                word &= word - 1;
                int j = w * 32 + bpos;
                int pj = g_parent[j];
                if (pj != ri && j != ri) uf_union(g_parent, ri, j);
            }
        }
    }
    grid_sync();

    // ---- phase 8: resolve — core final roots + border minima -----------------
    for (int i = wg; i < NPTS; i += CC_WARPS) {
        if (g_core[i]) {
            if (lane == 0) g_lbl[i] = uf_find(g_parent, i);
            continue;
        }
        int m = NPTS;
#pragma unroll
        for (int w = lane; w < DW; w += 32) {
            unsigned word = g_adj[i * DW + w] & g_corebits[w];
            while (word) {
                int bpos = __ffs(word) - 1;
                word &= word - 1;
                m = min(m, uf_find_ro(g_parent, w * 32 + bpos));
            }
        }
#pragma unroll
        for (int o = 16; o; o >>= 1) m = min(m, __shfl_down_sync(0xffffffffu, m, o));
        if (lane == 0) {
            g_root[i] = m;     // NPTS = noise
            g_lbl[i] = NPTS;
        }
    }
    grid_sync();

    // ---- phase 9: rank scan + final labels (block 0 only) --------------------
    if (blockIdx.x != 0) return;

    if (tid == 0) s_carry = 0;
    __syncthreads();

    for (int c = 0; c < 12; c++) {
        int e = c * 1024 + tid;
        int r = g_lbl[e];
        int v = (r == e) ? 1 : 0;               // is_root
        unsigned bal = __ballot_sync(0xffffffffu, v);
        int pre = __popc(bal & (0xffffffffu >> (31 - lane)));
        if (lane == 31) wsum[wid] = pre;
        __syncthreads();
        if (wid == 0) {
            int x = wsum[lane];
#pragma unroll
            for (int o = 1; o < 32; o <<= 1) {
                int y = __shfl_up_sync(0xffffffffu, x, o);
                if (lane >= o) x += y;
            }
            wsum[lane] = x;
        }
        __syncthreads();
        int base = s_carry + ((wid > 0) ? wsum[wid - 1] : 0);
        g_rank[e] = base + pre - 1;
        __syncthreads();
        if (tid == 0) s_carry += wsum[31];
        __syncthreads();
    }

    for (int c = 0; c < 12; c++) {
        int e = c * 1024 + tid;
        int r = g_lbl[e];
        if (r >= NPTS) r = g_root[e];           // border/noise
        labels[e] = (r < NPTS) ? g_rank[r] : -1;
    }
}

// ---------------- launcher ----------------------------------------------------
extern "C" void kernel_launch(void* const* d_in, const int* in_sizes, int n_in,
                              void* d_out, int out_size) {
    (void)in_sizes; (void)n_in; (void)out_size;
    const float* X = (const float*)d_in[0];
    int* labels = (int*)d_out;

    k_adj<<<NTRI, 256>>>(X);
    k_cc<<<CC_GRID, 1024>>>(labels);
}

// round 15
// speedup vs baseline: 1.1123x; 1.1087x over previous
#include <cuda_runtime.h>
#include <cstdint>

#define NPTS 12288
#define DW   384           // 32-bit words per adjacency row (12288/32)
#define EPS2 0.25f
#define MIN_SAMPLES 5
#define JT   256           // square tile side in k_adj
#define NTILE 48           // NPTS / JT
#define NTRI  (NTILE * (NTILE + 1) / 2)   // 1176 upper-tri tiles

#define CC_GRID   148
#define CC_WARPS  (CC_GRID * 32)          // 4736 global warps

typedef unsigned long long ull;

// ---------------- device scratch (no dynamic allocation allowed) -------------
__device__ __align__(16) unsigned g_adj[NPTS * DW];   // 18.9 MB adjacency bitmap
__device__ int      g_parent[NPTS];     // union-find parents
__device__ int      g_core[NPTS];       // core mask
__device__ unsigned g_corebits[DW];     // core mask, bit-packed
__device__ int      g_lbl[NPTS];        // final root per core (NPTS else)
__device__ int      g_root[NPTS];       // border root (non-core rows)
__device__ int      g_rank[NPTS];       // cumsum(is_root)-1

// software grid barrier state (generation-based; survives graph replays)
__device__ volatile int g_bar_gen;
__device__ int          g_bar_count;

// ---------------- f32x2 packed-math helpers (sm_100+) ------------------------
__device__ __forceinline__ ull pack2(float lo, float hi) {
    ull r;
    asm("mov.b64 %0, {%1, %2};" : "=l"(r) : "f"(lo), "f"(hi));
    return r;
}
__device__ __forceinline__ ull mul2(ull a, ull b) {
    ull d;
    asm("mul.rn.f32x2 %0, %1, %2;" : "=l"(d) : "l"(a), "l"(b));
    return d;
}
__device__ __forceinline__ ull fma2(ull a, ull b, ull c) {
    ull d;
    asm("fma.rn.f32x2 %0, %1, %2, %3;" : "=l"(d) : "l"(a), "l"(b), "l"(c));
    return d;
}
__device__ __forceinline__ ull add2(ull a, ull b) {
    ull d;
    asm("add.rn.f32x2 %0, %1, %2;" : "=l"(d) : "l"(a), "l"(b));
    return d;
}
__device__ __forceinline__ void unpack2(ull v, float& lo, float& hi) {
    asm("mov.b64 {%0, %1}, %2;" : "=f"(lo), "=f"(hi) : "l"(v));
}

__device__ __forceinline__ float norm8(float4 a, float4 b) {
    float s = a.x * a.x;
    s = fmaf(a.y, a.y, s);
    s = fmaf(a.z, a.z, s);
    s = fmaf(a.w, a.w, s);
    s = fmaf(b.x, b.x, s);
    s = fmaf(b.y, b.y, s);
    s = fmaf(b.z, b.z, s);
    s = fmaf(b.w, b.w, s);
    return s;
}

// 32x32 bit-matrix transpose within a warp (5 block-swap stages).
__device__ __forceinline__ unsigned bit_transpose32(unsigned x, int lane) {
    const unsigned masks[5] = {0xAAAAAAAAu, 0xCCCCCCCCu, 0xF0F0F0F0u,
                               0xFF00FF00u, 0xFFFF0000u};
#pragma unroll
    for (int si = 0; si < 5; si++) {
        int s = 1 << si;
        unsigned m = masks[si];
        unsigned y = __shfl_xor_sync(0xffffffffu, x, s);
        if (lane & s)
            x = (x & m) | ((y & m) >> s);
        else
            x = (x & ~m) | ((y & ~m) << s);
    }
    return x;
}

// ---------------- K1: adjacency bitmap (triangular; coalesced 128b stores) ---
// Compute identical to R12. Store path reworked:
//  - normal tile: stage words in smem (reusing sjd), then thread t writes row
//    t's 8 words as 2x STG.128  (2048 -> ~512 L1tex wavefronts per block)
//  - mirrored tile: lane already holds all 8 word-cols of one j-row after the
//    warp bit-transpose -> 2x STG.128 in-register merge (2048 -> 512 wf)
__global__ void __launch_bounds__(256) k_adj(const float* __restrict__ X) {
    // decode linear tile id -> (by, bx) with bx >= by (row-major upper tri)
    int tid_lin = blockIdx.x;
    float ff = __int2float_rn(tid_lin);
    int by = __float2int_rd((2.0f * NTILE + 1.0f -
                             sqrtf((2.0f * NTILE + 1.0f) * (2.0f * NTILE + 1.0f)
                                   - 8.0f * ff)) * 0.5f);
    while ((by + 1) * (2 * NTILE - by) / 2 <= tid_lin) by++;
    while (by * (2 * NTILE - by + 1) / 2 > tid_lin) by--;
    int bx = by + (tid_lin - by * (2 * NTILE - by + 1) / 2);

    __shared__ __align__(16) float4 sjd[JT][3];   // compute stage; reused as
                                                  // 256x8 word staging buffer

    int t = threadIdx.x;
    int jbase = bx * JT;
    int ibase = by * JT;
    const float4* xv = (const float4*)X;

    {
        float4 a = xv[(jbase + t) * 2 + 0];
        float4 b = xv[(jbase + t) * 2 + 1];
        sjd[t][0] = a;
        sjd[t][1] = b;
        sjd[t][2] = make_float4(norm8(a, b), 0.f, 0.f, 0.f);
    }
    __syncthreads();

    int wid = t >> 5, lane = t & 31;
    int i0 = ibase + lane;                    // rows i0 + 32r, r = 0..7

    ull rp[4][8], sid[4];
#pragma unroll
    for (int p = 0; p < 4; p++) {
        int ra = i0 + 32 * (2 * p), rb = i0 + 32 * (2 * p + 1);
        float4 a0 = xv[ra * 2 + 0], b0 = xv[ra * 2 + 1];
        float4 a1 = xv[rb * 2 + 0], b1 = xv[rb * 2 + 1];
        sid[p] = pack2(norm8(a0, b0), norm8(a1, b1));
        rp[p][0] = pack2(a0.x, a1.x); rp[p][1] = pack2(a0.y, a1.y);
        rp[p][2] = pack2(a0.z, a1.z); rp[p][3] = pack2(a0.w, a1.w);
        rp[p][4] = pack2(b0.x, b1.x); rp[p][5] = pack2(b0.y, b1.y);
        rp[p][6] = pack2(b0.z, b1.z); rp[p][7] = pack2(b0.w, b1.w);
    }
    ull neg2 = pack2(-2.0f, -2.0f);

    int kb = wid * 32;
    unsigned bits[8] = {0, 0, 0, 0, 0, 0, 0, 0};
#pragma unroll 4
    for (int k = 0; k < 32; k++) {
        float4 c = sjd[kb + k][0];
        float4 d = sjd[kb + k][1];
        float n  = sjd[kb + k][2].x;
        ull q0 = pack2(c.x, c.x), q1 = pack2(c.y, c.y);
        ull q2 = pack2(c.z, c.z), q3 = pack2(c.w, c.w);
        ull q4 = pack2(d.x, d.x), q5 = pack2(d.y, d.y);
        ull q6 = pack2(d.z, d.z), q7 = pack2(d.w, d.w);
        ull sq = pack2(n, n);
        unsigned kbit = 1u << k;
#pragma unroll
        for (int p = 0; p < 4; p++) {
            ull acc = mul2(rp[p][0], q0);
            acc = fma2(rp[p][1], q1, acc);
            acc = fma2(rp[p][2], q2, acc);
            acc = fma2(rp[p][3], q3, acc);
            acc = fma2(rp[p][4], q4, acc);
            acc = fma2(rp[p][5], q5, acc);
            acc = fma2(rp[p][6], q6, acc);
            acc = fma2(rp[p][7], q7, acc);
            ull t2 = fma2(acc, neg2, add2(sq, sid[p]));   // (si+sj) - 2*dot
            float lo, hi;
            unpack2(t2, lo, hi);
            if (lo <= EPS2) bits[2 * p]     |= kbit;
            if (hi <= EPS2) bits[2 * p + 1] |= kbit;
        }
    }

    // ---- mirrored tile first (uses bits in registers) ----
    if (bx != by) {
        unsigned tw[8];
#pragma unroll
        for (int r = 0; r < 8; r++)
            tw[r] = bit_transpose32(bits[r], lane);
        int jrow = jbase + kb + lane;
        uint4* dst = (uint4*)&g_adj[jrow * DW + by * 8];
        dst[0] = make_uint4(tw[0], tw[1], tw[2], tw[3]);
        dst[1] = make_uint4(tw[4], tw[5], tw[6], tw[7]);
    }

    // ---- normal tile via smem staging (reuse sjd; all reads of it done) ----
    __syncthreads();
    unsigned* sbuf = (unsigned*)sjd;          // 256 rows x 8 words = 8 KB
#pragma unroll
    for (int r = 0; r < 8; r++)
        sbuf[(lane + 32 * r) * 8 + wid] = bits[r];
    __syncthreads();
    {
        const uint4* s4 = (const uint4*)sbuf;
        uint4 a = s4[t * 2 + 0];
        uint4 b = s4[t * 2 + 1];
        uint4* dst = (uint4*)&g_adj[(ibase + t) * DW + bx * 8];
        dst[0] = a;
        dst[1] = b;
    }
}

// ---------------- union-find -------------------------------------------------
__device__ __forceinline__ int uf_find(volatile int* p, int x) {
    int px = p[x];
    while (px != x) {
        int g = p[px];
        if (g != px) p[x] = g;   // path halving; benign race
        x = g;
        px = p[x];
    }
    return x;
}

__device__ __forceinline__ void uf_union(int* p, int a, int b) {
    volatile int* vp = p;
    while (true) {
        a = uf_find(vp, a);
        b = uf_find(vp, b);
        if (a == b) return;
        int hi = a > b ? a : b;
        int lo = a > b ? b : a;
        int old = atomicCAS(&p[hi], hi, lo);
        if (old == hi) return;
        a = lo; b = old;
    }
}

__device__ __forceinline__ int uf_find_ro(const volatile int* p, int x) {
    int px;
    while ((px = p[x]) != x) x = px;
    return x;
}

// ---------------- software grid barrier (gen-based) ---------------------------
__device__ __forceinline__ void grid_sync() {
    __threadfence();
    __syncthreads();
    if (threadIdx.x == 0) {
        int gen = g_bar_gen;
        if (atomicAdd(&g_bar_count, 1) == (int)gridDim.x - 1) {
            g_bar_count = 0;
            __threadfence();
            g_bar_gen = gen + 1;
        } else {
            while (g_bar_gen == gen) { }
        }
    }
    __syncthreads();
    __threadfence();
}

// ---------------- K2: the whole CC pipeline in ONE persistent kernel ---------
__global__ void __launch_bounds__(1024, 1) k_cc(int* __restrict__ labels) {
    __shared__ int wsum[32];
    __shared__ int s_carry;

    int tid  = threadIdx.x;
    int lane = tid & 31;
    int wid  = tid >> 5;                     // warp in block, 0..31
    int wg   = blockIdx.x * 32 + wid;        // global warp, 0..4735
    int gtid = blockIdx.x * 1024 + tid;      // global thread

    // ---- phase 1: density -> core mask + parent init ------------------------
    for (int i = wg; i < NPTS; i += CC_WARPS) {
        const uint4* row = (const uint4*)&g_adj[i * DW];
        int s = 0;
#pragma unroll
        for (int w = lane; w < DW / 4; w += 32) {
            uint4 v = row[w];
            s += __popc(v.x) + __popc(v.y) + __popc(v.z) + __popc(v.w);
        }
#pragma unroll
        for (int o = 16; o; o >>= 1) s += __shfl_down_sync(0xffffffffu, s, o);
        if (lane == 0) {
            g_core[i] = (s >= MIN_SAMPLES) ? 1 : 0;
            g_parent[i] = i;
        }
    }
    grid_sync();

    // ---- phase 2: pack core bits --------------------------------------------
    if (wg < DW) {
        int c = g_core[wg * 32 + lane];
        unsigned b = __ballot_sync(0xffffffffu, c != 0);
        if (lane == 0) g_corebits[wg] = b;
    }
    grid_sync();

    // ---- phase 3: atomic-free forest init (first smaller core neighbor) -----
    for (int i = wg; i < NPTS; i += CC_WARPS) {
        if (!g_core[i]) continue;
        int iw = i >> 5;
        for (int base = 0; base <= iw; base += 32) {
            int w = base + lane;
            unsigned word = 0;
            if (w <= iw) {
                word = g_adj[i * DW + w] & g_corebits[w];
                if (w == iw) {
                    int r = i & 31;
                    word &= r ? ((1u << r) - 1u) : 0u;   // only j < i
                }
            }
            unsigned nz = __ballot_sync(0xffffffffu, word != 0);
            if (nz) {
                int w0 = __ffs(nz) - 1;
                unsigned v0 = __shfl_sync(0xffffffffu, word, w0);
                if (lane == 0) g_parent[i] = (base + w0) * 32 + __ffs(v0) - 1;
                break;
            }
        }
    }
    grid_sync();

    // ---- phase 4: flatten (race-free: no hooks in flight) --------------------
    if (gtid < NPTS && g_core[gtid]) g_parent[gtid] = uf_find_ro(g_parent, gtid);
    grid_sync();

    // ---- phase 5: hook — min neighbor root via ONE atomicMin -----------------
    for (int i = wg; i < NPTS; i += CC_WARPS) {
        if (!g_core[i]) continue;
        int ri = g_parent[i];
        int m = ri;
#pragma unroll
        for (int w = lane; w < DW; w += 32) {
            unsigned word = g_adj[i * DW + w] & g_corebits[w];
            while (word) {
                int bpos = __ffs(word) - 1;
                word &= word - 1;
                m = min(m, g_parent[w * 32 + bpos]);
            }
        }
#pragma unroll
        for (int o = 16; o; o >>= 1) m = min(m, __shfl_down_sync(0xffffffffu, m, o));
        if (lane == 0 && m < ri) atomicMin(&g_parent[ri], m);
    }
    grid_sync();

    // ---- phase 6: flatten ----------------------------------------------------
    if (gtid < NPTS && g_core[gtid]) g_parent[gtid] = uf_find_ro(g_parent, gtid);
    grid_sync();

    // ---- phase 7: full edge pass (guaranteed closer; nearly all skip) --------
    for (int i = wg; i < NPTS; i += CC_WARPS) {
        if (!g_core[i]) continue;
        int ri = uf_find(g_parent, i);
        int iw = i >> 5;
        for (int w = iw + lane; w < DW; w += 32) {
            unsigned word = g_adj[i * DW + w] & g_corebits[w];
            if (w == iw) {
                int r = i & 31;
                word &= (r == 31) ? 0u : (0xffffffffu << (r + 1));   // only j > i
            }
            while (word) {
                int bpos = __ffs(word) - 1;
                word &= word - 1;
                int j = w * 32 + bpos;
                int pj = g_parent[j];
                if (pj != ri && j != ri) uf_union(g_parent, ri, j);
            }
        }
    }
    grid_sync();

    // ---- phase 8: resolve — core final roots + border minima -----------------
    for (int i = wg; i < NPTS; i += CC_WARPS) {
        if (g_core[i]) {
            if (lane == 0) g_lbl[i] = uf_find(g_parent, i);
            continue;
        }
        int m = NPTS;
#pragma unroll
        for (int w = lane; w < DW; w += 32) {
            unsigned word = g_adj[i * DW + w] & g_corebits[w];
            while (word) {
                int bpos = __ffs(word) - 1;
                word &= word - 1;
                m = min(m, uf_find_ro(g_parent, w * 32 + bpos));
            }
        }
#pragma unroll
        for (int o = 16; o; o >>= 1) m = min(m, __shfl_down_sync(0xffffffffu, m, o));
        if (lane == 0) {
            g_root[i] = m;     // NPTS = noise
            g_lbl[i] = NPTS;
        }
    }
    grid_sync();

    // ---- phase 9: rank scan + final labels (block 0 only) --------------------
    if (blockIdx.x != 0) return;

    if (tid == 0) s_carry = 0;
    __syncthreads();

    for (int c = 0; c < 12; c++) {
        int e = c * 1024 + tid;
        int r = g_lbl[e];
        int v = (r == e) ? 1 : 0;               // is_root
        unsigned bal = __ballot_sync(0xffffffffu, v);
        int pre = __popc(bal & (0xffffffffu >> (31 - lane)));
        if (lane == 31) wsum[wid] = pre;
        __syncthreads();
        if (wid == 0) {
            int x = wsum[lane];
#pragma unroll
            for (int o = 1; o < 32; o <<= 1) {
                int y = __shfl_up_sync(0xffffffffu, x, o);
                if (lane >= o) x += y;
            }
            wsum[lane] = x;
        }
        __syncthreads();
        int base = s_carry + ((wid > 0) ? wsum[wid - 1] : 0);
        g_rank[e] = base + pre - 1;
        __syncthreads();
        if (tid == 0) s_carry += wsum[31];
        __syncthreads();
    }

    for (int c = 0; c < 12; c++) {
        int e = c * 1024 + tid;
        int r = g_lbl[e];
        if (r >= NPTS) r = g_root[e];           // border/noise
        labels[e] = (r < NPTS) ? g_rank[r] : -1;
    }
}

// ---------------- launcher ----------------------------------------------------
extern "C" void kernel_launch(void* const* d_in, const int* in_sizes, int n_in,
                              void* d_out, int out_size) {
    (void)in_sizes; (void)n_in; (void)out_size;
    const float* X = (const float*)d_in[0];
    int* labels = (int*)d_out;

    k_adj<<<NTRI, 256>>>(X);
    k_cc<<<CC_GRID, 1024>>>(labels);
}